// round 2
// baseline (speedup 1.0000x reference)
#include <cuda_runtime.h>

#define B_DIM   1024
#define C_DIM   64
#define W_DIM   40
#define NCLS    512
#define P_DIM   20480   // NCLS * W_DIM

// Scratch (device globals; no allocation allowed)
__device__ float g_xn[B_DIM * C_DIM * W_DIM];   // normalized conv, layout [b][c][w]
__device__ float g_pn[NCLS * C_DIM * W_DIM];    // normalized prototypes, layout [k][c][i]
__device__ float g_scls[B_DIM * NCLS];          // per-class sim sums

// ---------------------------------------------------------------------------
// K1: L2-normalize conv_features over C for each (b, w). Layout preserved.
// ---------------------------------------------------------------------------
__global__ void k_norm_x(const float* __restrict__ conv) {
    __shared__ float sx[C_DIM * W_DIM];
    __shared__ float sinv[W_DIM];
    const int b = blockIdx.x;
    const int t = threadIdx.x;
    const float* src = conv + b * (C_DIM * W_DIM);
    for (int j = t; j < C_DIM * W_DIM; j += 256) sx[j] = src[j];
    __syncthreads();
    if (t < W_DIM) {
        float ss = 0.f;
        #pragma unroll
        for (int c = 0; c < C_DIM; c++) { float v = sx[c * W_DIM + t]; ss += v * v; }
        sinv[t] = 1.f / fmaxf(sqrtf(ss), 1e-12f);
    }
    __syncthreads();
    float* dst = g_xn + b * (C_DIM * W_DIM);
    for (int j = t; j < C_DIM * W_DIM; j += 256) dst[j] = sx[j] * sinv[j % W_DIM];
}

// ---------------------------------------------------------------------------
// K2: L2-normalize prototypes over C and transpose to [k][c][i], i = p % 40.
// ---------------------------------------------------------------------------
__global__ void k_norm_p(const float* __restrict__ proto) {
    __shared__ float sp[W_DIM * 66];
    __shared__ float sinv[W_DIM];
    const int k = blockIdx.x;
    const int t = threadIdx.x;
    const float* src = proto + k * (W_DIM * C_DIM);
    for (int m = t; m < W_DIM * C_DIM; m += 256)
        sp[(m >> 6) * 66 + (m & 63)] = src[m];
    __syncthreads();
    if (t < W_DIM) {
        float ss = 0.f;
        #pragma unroll
        for (int c = 0; c < C_DIM; c++) { float v = sp[t * 66 + c]; ss += v * v; }
        sinv[t] = 1.f / fmaxf(sqrtf(ss), 1e-12f);
    }
    __syncthreads();
    float* dst = g_pn + k * (C_DIM * W_DIM);   // [c][i]
    for (int j = t; j < C_DIM * W_DIM; j += 256) {
        int c = j / W_DIM;
        int i = j - c * W_DIM;
        dst[j] = sp[i * 66 + c] * sinv[i];
    }
}

// ---------------------------------------------------------------------------
// K3: sim[b][k][i] = sum_c xn[b][c][i] * pn[k][c][i]
// Block tile: 32 b x 32 k x all 40 i.  320 threads = (tb 4) x (tk 4) x (ti 20).
// Thread microtile: 8b x 8k x 2i (one f32x2 accumulator per (b,k)).
// Reuse ratio = 2*8*8/(8+8) = 8 FFMA2 per LDS.64 -> FMA/smem balanced.
// ---------------------------------------------------------------------------
#define BT  32
#define KT  32
#define CCH 4

__global__ __launch_bounds__(320, 1) void k_gemm(float* __restrict__ md) {
    __shared__ float Xs[CCH * BT * W_DIM];   // [cc][bb][i]  5120 floats (20KB)
    __shared__ float Ps[CCH * KT * W_DIM];   // [cc][kk][i]  5120 floats (20KB)

    const int t  = threadIdx.x;
    const int ti = t % 20;                   // i pair: i = ti*2
    const int tk = (t / 20) % 4;             // k group base tk*8
    const int tb = t / 80;                   // b group base tb*8
    const int b0 = blockIdx.x * BT;
    const int k0 = blockIdx.y * KT;
    const int i2 = ti * 2;

    unsigned long long acc[8][8];
    #pragma unroll
    for (int rb = 0; rb < 8; rb++)
        #pragma unroll
        for (int rk = 0; rk < 8; rk++) acc[rb][rk] = 0ull;

    for (int c0 = 0; c0 < C_DIM; c0 += CCH) {
        // cooperative tile copy: 1280 float4 each
        #pragma unroll
        for (int m = t; m < CCH * BT * 10; m += 320) {
            int cc = m / (BT * 10);
            int r  = m - cc * (BT * 10);
            int bb = r / 10;
            int iq = r - bb * 10;
            reinterpret_cast<float4*>(Xs)[m] =
                *reinterpret_cast<const float4*>(
                    &g_xn[(b0 + bb) * (C_DIM * W_DIM) + (c0 + cc) * W_DIM + iq * 4]);
        }
        #pragma unroll
        for (int m = t; m < CCH * KT * 10; m += 320) {
            int cc = m / (KT * 10);
            int r  = m - cc * (KT * 10);
            int kk = r / 10;
            int iq = r - kk * 10;
            reinterpret_cast<float4*>(Ps)[m] =
                *reinterpret_cast<const float4*>(
                    &g_pn[(k0 + kk) * (C_DIM * W_DIM) + (c0 + cc) * W_DIM + iq * 4]);
        }
        __syncthreads();

        #pragma unroll
        for (int cc = 0; cc < CCH; cc++) {
            unsigned long long xf[8], pf[8];
            #pragma unroll
            for (int rb = 0; rb < 8; rb++)
                xf[rb] = *reinterpret_cast<const unsigned long long*>(
                    &Xs[(cc * BT + tb * 8 + rb) * W_DIM + i2]);
            #pragma unroll
            for (int rk = 0; rk < 8; rk++)
                pf[rk] = *reinterpret_cast<const unsigned long long*>(
                    &Ps[(cc * KT + tk * 8 + rk) * W_DIM + i2]);
            #pragma unroll
            for (int rb = 0; rb < 8; rb++)
                #pragma unroll
                for (int rk = 0; rk < 8; rk++)
                    asm("fma.rn.f32x2 %0, %1, %2, %0;"
                        : "+l"(acc[rb][rk]) : "l"(xf[rb]), "l"(pf[rk]));
        }
        __syncthreads();
    }

    // ---- Epilogue ----
    // (a) streaming store of min_distances = -sim
    #pragma unroll
    for (int rb = 0; rb < 8; rb++) {
        const int b = b0 + tb * 8 + rb;
        #pragma unroll
        for (int rk = 0; rk < 8; rk++) {
            const int k = k0 + tk * 8 + rk;
            float f0 = __uint_as_float((unsigned)(acc[rb][rk]));
            float f1 = __uint_as_float((unsigned)(acc[rb][rk] >> 32));
            float2 o = make_float2(-f0, -f1);
            __stcs(reinterpret_cast<float2*>(&md[(size_t)b * P_DIM + k * W_DIM + i2]), o);
        }
    }

    // (b) class partial sums: 8 passes over rb, reduce over 20 ti-threads.
    // Buffer stride 21 -> conflict-free (gcd(21,32)=1). 128 pairs * 21 floats.
    float* red = Xs;   // reuse (needs 2688 <= 5120 floats)
    #pragma unroll 1
    for (int rb = 0; rb < 8; rb++) {
        __syncthreads();
        #pragma unroll
        for (int rk = 0; rk < 8; rk++) {
            float f0 = __uint_as_float((unsigned)(acc[rb][rk]));
            float f1 = __uint_as_float((unsigned)(acc[rb][rk] >> 32));
            int pid = tb * KT + tk * 8 + rk;           // 0..127
            red[pid * 21 + ti] = f0 + f1;
        }
        __syncthreads();
        if (t < 4 * KT) {                              // 128 active threads
            float s = 0.f;
            #pragma unroll
            for (int q = 0; q < 20; q++) s += red[t * 21 + q];
            int tbq = t / KT;
            int kk  = t - tbq * KT;
            g_scls[(size_t)(b0 + tbq * 8 + rb) * NCLS + k0 + kk] = s;
        }
    }
}

// ---------------------------------------------------------------------------
// K4: logits[b][cls] = 1.5*S_cls - 0.5*S_total   (shuffle-based reduction)
// ---------------------------------------------------------------------------
__global__ void k_logits(float* __restrict__ out) {
    __shared__ float ws[16];
    __shared__ float totsh;
    const int b = blockIdx.x;
    const int t = threadIdx.x;           // 512
    float s = g_scls[b * NCLS + t];
    float w = s;
    #pragma unroll
    for (int off = 16; off > 0; off >>= 1) w += __shfl_xor_sync(0xffffffffu, w, off);
    if ((t & 31) == 0) ws[t >> 5] = w;
    __syncthreads();
    if (t < 32) {
        float v = (t < 16) ? ws[t] : 0.f;
        #pragma unroll
        for (int off = 8; off > 0; off >>= 1) v += __shfl_xor_sync(0xffffffffu, v, off);
        if (t == 0) totsh = v;
    }
    __syncthreads();
    out[b * NCLS + t] = 1.5f * s - 0.5f * totsh;
}

// ---------------------------------------------------------------------------
extern "C" void kernel_launch(void* const* d_in, const int* in_sizes, int n_in,
                              void* d_out, int out_size) {
    const float* conv  = (const float*)d_in[0];   // (1024, 64, 1, 40)
    const float* proto = (const float*)d_in[1];   // (20480, 64, 1, 1)
    // d_in[2] (last_layer_weight) and d_in[3] (offset_tensor) are analytic — unused.

    float* out    = (float*)d_out;
    float* logits = out;                                // (1024, 512)
    float* md     = out + (size_t)B_DIM * NCLS;         // (1024, 20480)

    k_norm_x<<<B_DIM, 256>>>(conv);
    k_norm_p<<<NCLS, 256>>>(proto);
    k_gemm<<<dim3(B_DIM / BT, NCLS / KT), 320>>>(md);
    k_logits<<<B_DIM, 512>>>(logits);
}

// round 4
// speedup vs baseline: 3.2613x; 3.2613x over previous
#include <cuda_runtime.h>
#include <cuda_bf16.h>
#include <cstdint>

#define NB 1024
#define NC 64
#define NI 40
#define NK 512
#define NP 20480   // NK * NI

// ---------------- device scratch (no allocation allowed) ----------------
__device__ __align__(16) __nv_bfloat16 g_xhi[NI * NB * NC];   // [i][b][c]
__device__ __align__(16) __nv_bfloat16 g_xlo[NI * NB * NC];
__device__ __align__(16) __nv_bfloat16 g_phi[NI * NK * NC];   // [i][k][c]
__device__ __align__(16) __nv_bfloat16 g_plo[NI * NK * NC];
__device__ __align__(16) float g_sim[(size_t)NI * NB * NK];   // [i][b][k]

// SW128 swizzle on byte offsets (128B rows)
#define SW128(o) ((o) ^ (((o) >> 3) & 0x70))

__device__ __forceinline__ uint32_t smem_u32(const void* p) {
    uint32_t a;
    asm("{ .reg .u64 t; cvta.to.shared.u64 t, %1; cvt.u32.u64 %0, t; }" : "=r"(a) : "l"(p));
    return a;
}
__device__ __forceinline__ void ldsm_x4(uint32_t* r, uint32_t addr) {
    asm volatile("ldmatrix.sync.aligned.m8n8.x4.shared.b16 {%0,%1,%2,%3}, [%4];"
                 : "=r"(r[0]), "=r"(r[1]), "=r"(r[2]), "=r"(r[3]) : "r"(addr));
}
__device__ __forceinline__ void mma16816(float* c, const uint32_t* a, const uint32_t* b) {
    asm volatile(
        "mma.sync.aligned.m16n8k16.row.col.f32.bf16.bf16.f32 "
        "{%0,%1,%2,%3}, {%4,%5,%6,%7}, {%8,%9}, {%0,%1,%2,%3};"
        : "+f"(c[0]), "+f"(c[1]), "+f"(c[2]), "+f"(c[3])
        : "r"(a[0]), "r"(a[1]), "r"(a[2]), "r"(a[3]), "r"(b[0]), "r"(b[1]));
}

// ---------------------------------------------------------------------------
// K1: normalize x over C, split bf16 hi/lo, write [i=w][b][c]
// ---------------------------------------------------------------------------
__global__ void k_prep_x(const float* __restrict__ conv) {
    __shared__ float sx[NC * NI];
    __shared__ float sinv[NI];
    const int b = blockIdx.x, t = threadIdx.x;
    const float* src = conv + (size_t)b * NC * NI;
    for (int j = t; j < NC * NI; j += 256) sx[j] = src[j];
    __syncthreads();
    if (t < NI) {
        float ss = 0.f;
        #pragma unroll
        for (int c = 0; c < NC; c++) { float v = sx[c * NI + t]; ss += v * v; }
        sinv[t] = 1.f / fmaxf(sqrtf(ss), 1e-12f);
    }
    __syncthreads();
    for (int j = t; j < NI * NC; j += 256) {
        int w = j >> 6, c = j & 63;
        float val = sx[c * NI + w] * sinv[w];
        __nv_bfloat16 hi = __float2bfloat16(val);
        __nv_bfloat16 lo = __float2bfloat16(val - __bfloat162float(hi));
        size_t o = ((size_t)w * NB + b) * NC + c;
        g_xhi[o] = hi; g_xlo[o] = lo;
    }
}

// ---------------------------------------------------------------------------
// K2: normalize prototypes over C, split bf16 hi/lo, write [i][k][c]
// ---------------------------------------------------------------------------
__global__ void k_prep_p(const float* __restrict__ proto) {
    __shared__ float sq[256];
    __shared__ float sinv[4];
    const int t = threadIdx.x;
    const int p = blockIdx.x * 4 + (t >> 6);
    const int c = t & 63;
    float v = proto[(size_t)p * NC + c];
    sq[t] = v * v;
    __syncthreads();
    if ((t & 63) < 32) {
        float w = sq[t] + sq[t + 32];
        #pragma unroll
        for (int off = 16; off > 0; off >>= 1) w += __shfl_xor_sync(0xffffffffu, w, off);
        if ((t & 31) == 0) sinv[t >> 6] = 1.f / fmaxf(sqrtf(w), 1e-12f);
    }
    __syncthreads();
    float val = v * sinv[t >> 6];
    __nv_bfloat16 hi = __float2bfloat16(val);
    __nv_bfloat16 lo = __float2bfloat16(val - __bfloat162float(hi));
    const int k = p / NI, i = p - k * NI;
    size_t o = ((size_t)i * NK + k) * NC + c;
    g_phi[o] = hi; g_plo[o] = lo;
}

// ---------------------------------------------------------------------------
// K3: bf16 mma.sync GEMM. CTA: 128 threads (2x2 warps), tile 128b x 64k, one i.
// K=64 entirely resident in smem; 3 split products (hh, hl, lh) accumulated
// in fp32. Smem (dynamic, 48KB): A_hi 16K | A_lo 16K | B_hi 8K | B_lo 8K.
// ---------------------------------------------------------------------------
#define OFF_AHI 0
#define OFF_ALO 16384
#define OFF_BHI 32768
#define OFF_BLO 40960
#define GEMM_SMEM 49152

__global__ void __launch_bounds__(128, 4) k_gemm_mma() {
    extern __shared__ uint8_t dsm[];
    const int t = threadIdx.x, lane = t & 31, wid = t >> 5;
    const int wm = wid >> 1, wn = wid & 1;          // warp grid 2x2
    const int i  = blockIdx.z;
    const int b0 = blockIdx.x * 128;
    const int k0 = blockIdx.y * 64;

    // ---- load tiles (SW128-swizzled, 16B chunks) ----
    {
        const float4* axh = reinterpret_cast<const float4*>(g_xhi + ((size_t)i * NB + b0) * NC);
        const float4* axl = reinterpret_cast<const float4*>(g_xlo + ((size_t)i * NB + b0) * NC);
        for (int m = t; m < 1024; m += 128) {
            uint32_t so = SW128(m * 16);
            *reinterpret_cast<float4*>(dsm + OFF_AHI + so) = axh[m];
            *reinterpret_cast<float4*>(dsm + OFF_ALO + so) = axl[m];
        }
        const float4* bph = reinterpret_cast<const float4*>(g_phi + ((size_t)i * NK + k0) * NC);
        const float4* bpl = reinterpret_cast<const float4*>(g_plo + ((size_t)i * NK + k0) * NC);
        for (int m = t; m < 512; m += 128) {
            uint32_t so = SW128(m * 16);
            *reinterpret_cast<float4*>(dsm + OFF_BHI + so) = bph[m];
            *reinterpret_cast<float4*>(dsm + OFF_BLO + so) = bpl[m];
        }
    }
    __syncthreads();

    // lane decomposition for ldmatrix addressing
    const int r8 = lane & 7, g = lane >> 3;
    const uint32_t a_row = (uint32_t)(wm * 64 + (g & 1) * 8 + r8);   // A row within 128
    const uint32_t a_kh  = (uint32_t)(g >> 1);                        // k-chunk half
    const uint32_t b_row = (uint32_t)(wn * 32 + (g >> 1) * 8 + r8);  // B row (n) within 64
    const uint32_t b_kh  = (uint32_t)(g & 1);
    const uint32_t sbase = smem_u32(dsm);

    float acc[4][4][4];
    #pragma unroll
    for (int mt = 0; mt < 4; mt++)
        #pragma unroll
        for (int nt = 0; nt < 4; nt++)
            #pragma unroll
            for (int q = 0; q < 4; q++) acc[mt][nt][q] = 0.f;

    #pragma unroll
    for (int prod = 0; prod < 3; prod++) {
        const uint32_t Ab = sbase + (prod == 2 ? OFF_ALO : OFF_AHI);
        const uint32_t Bb = sbase + (prod == 1 ? OFF_BLO : OFF_BHI);
        #pragma unroll
        for (int kc = 0; kc < 4; kc++) {
            uint32_t af[4][4], bf[4][2];
            #pragma unroll
            for (int mt = 0; mt < 4; mt++) {
                uint32_t bo = (a_row + mt * 16) * 128 + (kc * 2 + a_kh) * 16;
                ldsm_x4(af[mt], Ab + SW128(bo));
            }
            #pragma unroll
            for (int np = 0; np < 2; np++) {
                uint32_t r[4];
                uint32_t bo = (b_row + np * 16) * 128 + (kc * 2 + b_kh) * 16;
                ldsm_x4(r, Bb + SW128(bo));
                bf[2 * np][0] = r[0]; bf[2 * np][1] = r[1];
                bf[2 * np + 1][0] = r[2]; bf[2 * np + 1][1] = r[3];
            }
            #pragma unroll
            for (int mt = 0; mt < 4; mt++)
                #pragma unroll
                for (int nt = 0; nt < 4; nt++)
                    mma16816(acc[mt][nt], af[mt], bf[nt]);
        }
    }

    // ---- epilogue: store to g_sim[i][b][k] ----
    const int row_base = b0 + wm * 64 + (lane >> 2);
    const int col_base = k0 + wn * 32 + (lane & 3) * 2;
    #pragma unroll
    for (int mt = 0; mt < 4; mt++) {
        #pragma unroll
        for (int nt = 0; nt < 4; nt++) {
            size_t o0 = ((size_t)i * NB + row_base + mt * 16) * NK + col_base + nt * 8;
            *reinterpret_cast<float2*>(g_sim + o0) =
                make_float2(acc[mt][nt][0], acc[mt][nt][1]);
            *reinterpret_cast<float2*>(g_sim + o0 + 8 * NK) =
                make_float2(acc[mt][nt][2], acc[mt][nt][3]);
        }
    }
}

// ---------------------------------------------------------------------------
// K4: transpose [i][b][k] -> md[b][k*40+i] = -sim ; fused class sums + logits
// ---------------------------------------------------------------------------
__global__ void k_trans(float* __restrict__ md, float* __restrict__ logits) {
    __shared__ float tile[256 * 41];
    __shared__ float cls[NK];
    __shared__ float ws[8];
    __shared__ float totsh;
    const int b = blockIdx.x, t = threadIdx.x;   // 256 threads

    for (int kc = 0; kc < 2; kc++) {
        const int k0 = kc * 256;
        float s = 0.f;
        #pragma unroll
        for (int i = 0; i < NI; i++) {
            float v = g_sim[((size_t)i * NB + b) * NK + k0 + t];
            tile[t * 41 + i] = v;
            s += v;
        }
        cls[k0 + t] = s;
        __syncthreads();
        float4* dst = reinterpret_cast<float4*>(md + (size_t)b * NP + k0 * NI);
        for (int m = t; m < 2560; m += 256) {
            int kl = m / 10, r4 = (m % 10) * 4;
            const float* sp = &tile[kl * 41 + r4];
            dst[m] = make_float4(-sp[0], -sp[1], -sp[2], -sp[3]);
        }
        __syncthreads();
    }

    float s0 = cls[t], s1 = cls[t + 256];
    float w = s0 + s1;
    #pragma unroll
    for (int off = 16; off > 0; off >>= 1) w += __shfl_xor_sync(0xffffffffu, w, off);
    if ((t & 31) == 0) ws[t >> 5] = w;
    __syncthreads();
    if (t < 32) {
        float v = (t < 8) ? ws[t] : 0.f;
        #pragma unroll
        for (int off = 4; off > 0; off >>= 1) v += __shfl_xor_sync(0xffffffffu, v, off);
        if (t == 0) totsh = v;
    }
    __syncthreads();
    const float tot = totsh;
    logits[(size_t)b * NK + t]       = 1.5f * s0 - 0.5f * tot;
    logits[(size_t)b * NK + t + 256] = 1.5f * s1 - 0.5f * tot;
}

// ---------------------------------------------------------------------------
extern "C" void kernel_launch(void* const* d_in, const int* in_sizes, int n_in,
                              void* d_out, int out_size) {
    const float* conv  = (const float*)d_in[0];   // (1024, 64, 1, 40)
    const float* proto = (const float*)d_in[1];   // (20480, 64, 1, 1)
    // d_in[2], d_in[3] analytic — unused.

    float* out    = (float*)d_out;
    float* logits = out;                                // (1024, 512)
    float* md     = out + (size_t)NB * NK;              // (1024, 20480)

    cudaFuncSetAttribute(k_gemm_mma, cudaFuncAttributeMaxDynamicSharedMemorySize, GEMM_SMEM);

    k_prep_x<<<NB, 256>>>(conv);
    k_prep_p<<<NP / 4, 256>>>(proto);
    k_gemm_mma<<<dim3(8, 8, NI), 128, GEMM_SMEM>>>();
    k_trans<<<NB, 256>>>(md, logits);
}

// round 5
// speedup vs baseline: 3.9468x; 1.2102x over previous
#include <cuda_runtime.h>
#include <cuda_fp16.h>
#include <cstdint>

#define NB 1024
#define NC 64
#define NI 40
#define NK 512
#define NP 20480   // NK * NI

// ---------------- device scratch (no allocation allowed) ----------------
__device__ __align__(16) __half g_xh[NI * NB * NC];           // [i][b][c]
__device__ __align__(16) __half g_ph[NI * NK * NC];           // [i][k][c]
__device__ __align__(16) float g_sim[(size_t)NI * NB * NK];   // [i][b][k]

// SW128 swizzle on byte offsets (128B rows)
#define SW128(o) ((o) ^ (((o) >> 3) & 0x70))

__device__ __forceinline__ uint32_t smem_u32(const void* p) {
    uint32_t a;
    asm("{ .reg .u64 t; cvta.to.shared.u64 t, %1; cvt.u32.u64 %0, t; }" : "=r"(a) : "l"(p));
    return a;
}
__device__ __forceinline__ void ldsm_x4(uint32_t* r, uint32_t addr) {
    asm volatile("ldmatrix.sync.aligned.m8n8.x4.shared.b16 {%0,%1,%2,%3}, [%4];"
                 : "=r"(r[0]), "=r"(r[1]), "=r"(r[2]), "=r"(r[3]) : "r"(addr));
}
__device__ __forceinline__ void mma16816(float* c, const uint32_t* a, const uint32_t* b) {
    asm volatile(
        "mma.sync.aligned.m16n8k16.row.col.f32.f16.f16.f32 "
        "{%0,%1,%2,%3}, {%4,%5,%6,%7}, {%8,%9}, {%0,%1,%2,%3};"
        : "+f"(c[0]), "+f"(c[1]), "+f"(c[2]), "+f"(c[3])
        : "r"(a[0]), "r"(a[1]), "r"(a[2]), "r"(a[3]), "r"(b[0]), "r"(b[1]));
}

// ---------------------------------------------------------------------------
// K1: normalize x over C, convert fp16, write [i=w][b][c]
// ---------------------------------------------------------------------------
__global__ void k_prep_x(const float* __restrict__ conv) {
    __shared__ float sx[NC * NI];
    __shared__ float sinv[NI];
    const int b = blockIdx.x, t = threadIdx.x;
    const float* src = conv + (size_t)b * NC * NI;
    for (int j = t; j < NC * NI; j += 256) sx[j] = src[j];
    __syncthreads();
    if (t < NI) {
        float ss = 0.f;
        #pragma unroll
        for (int c = 0; c < NC; c++) { float v = sx[c * NI + t]; ss += v * v; }
        sinv[t] = 1.f / fmaxf(sqrtf(ss), 1e-12f);
    }
    __syncthreads();
    for (int j = t; j < NI * NC; j += 256) {
        int w = j >> 6, c = j & 63;
        float val = sx[c * NI + w] * sinv[w];
        g_xh[((size_t)w * NB + b) * NC + c] = __float2half_rn(val);
    }
}

// ---------------------------------------------------------------------------
// K2: normalize prototypes over C, convert fp16, write [i][k][c]
// ---------------------------------------------------------------------------
__global__ void k_prep_p(const float* __restrict__ proto) {
    __shared__ float sq[256];
    __shared__ float sinv[4];
    const int t = threadIdx.x;
    const int p = blockIdx.x * 4 + (t >> 6);
    const int c = t & 63;
    float v = proto[(size_t)p * NC + c];
    sq[t] = v * v;
    __syncthreads();
    if ((t & 63) < 32) {
        float w = sq[t] + sq[t + 32];
        #pragma unroll
        for (int off = 16; off > 0; off >>= 1) w += __shfl_xor_sync(0xffffffffu, w, off);
        if ((t & 31) == 0) sinv[t >> 6] = 1.f / fmaxf(sqrtf(w), 1e-12f);
    }
    __syncthreads();
    float val = v * sinv[t >> 6];
    const int k = p / NI, i = p - k * NI;
    g_ph[((size_t)i * NK + k) * NC + c] = __float2half_rn(val);
}

// ---------------------------------------------------------------------------
// K3: fp16 mma.sync GEMM (single product). CTA: 128 threads (2x2 warps),
// tile 128b x 64k, one i; K=64 resident. Smem 24KB: A 16K | B 8K.
// ---------------------------------------------------------------------------
#define OFF_A 0
#define OFF_B 16384
#define GEMM_SMEM 24576

__global__ void __launch_bounds__(128, 4) k_gemm_mma() {
    extern __shared__ uint8_t dsm[];
    const int t = threadIdx.x, lane = t & 31, wid = t >> 5;
    const int wm = wid >> 1, wn = wid & 1;          // warp grid 2x2
    const int i  = blockIdx.z;
    const int b0 = blockIdx.x * 128;
    const int k0 = blockIdx.y * 64;

    // ---- load tiles (SW128-swizzled, 16B chunks) ----
    {
        const float4* ax = reinterpret_cast<const float4*>(g_xh + ((size_t)i * NB + b0) * NC);
        for (int m = t; m < 1024; m += 128)
            *reinterpret_cast<float4*>(dsm + OFF_A + SW128(m * 16)) = ax[m];
        const float4* bp = reinterpret_cast<const float4*>(g_ph + ((size_t)i * NK + k0) * NC);
        for (int m = t; m < 512; m += 128)
            *reinterpret_cast<float4*>(dsm + OFF_B + SW128(m * 16)) = bp[m];
    }
    __syncthreads();

    // lane decomposition for ldmatrix addressing
    const int r8 = lane & 7, g = lane >> 3;
    const uint32_t a_row = (uint32_t)(wm * 64 + (g & 1) * 8 + r8);   // A row within 128
    const uint32_t a_kh  = (uint32_t)(g >> 1);                        // k-chunk half
    const uint32_t b_row = (uint32_t)(wn * 32 + (g >> 1) * 8 + r8);  // B row (n) within 64
    const uint32_t b_kh  = (uint32_t)(g & 1);
    const uint32_t sbase = smem_u32(dsm);

    float acc[4][4][4];
    #pragma unroll
    for (int mt = 0; mt < 4; mt++)
        #pragma unroll
        for (int nt = 0; nt < 4; nt++)
            #pragma unroll
            for (int q = 0; q < 4; q++) acc[mt][nt][q] = 0.f;

    #pragma unroll
    for (int kc = 0; kc < 4; kc++) {
        uint32_t af[4][4], bf[4][2];
        #pragma unroll
        for (int mt = 0; mt < 4; mt++) {
            uint32_t bo = (a_row + mt * 16) * 128 + (kc * 2 + a_kh) * 16;
            ldsm_x4(af[mt], sbase + OFF_A + SW128(bo));
        }
        #pragma unroll
        for (int np = 0; np < 2; np++) {
            uint32_t r[4];
            uint32_t bo = (b_row + np * 16) * 128 + (kc * 2 + b_kh) * 16;
            ldsm_x4(r, sbase + OFF_B + SW128(bo));
            bf[2 * np][0] = r[0]; bf[2 * np][1] = r[1];
            bf[2 * np + 1][0] = r[2]; bf[2 * np + 1][1] = r[3];
        }
        #pragma unroll
        for (int mt = 0; mt < 4; mt++)
            #pragma unroll
            for (int nt = 0; nt < 4; nt++)
                mma16816(acc[mt][nt], af[mt], bf[nt]);
    }

    // ---- epilogue: store to g_sim[i][b][k] (default caching -> L2 resident) ----
    const int row_base = b0 + wm * 64 + (lane >> 2);
    const int col_base = k0 + wn * 32 + (lane & 3) * 2;
    #pragma unroll
    for (int mt = 0; mt < 4; mt++) {
        #pragma unroll
        for (int nt = 0; nt < 4; nt++) {
            size_t o0 = ((size_t)i * NB + row_base + mt * 16) * NK + col_base + nt * 8;
            *reinterpret_cast<float2*>(g_sim + o0) =
                make_float2(acc[mt][nt][0], acc[mt][nt][1]);
            *reinterpret_cast<float2*>(g_sim + o0 + 8 * NK) =
                make_float2(acc[mt][nt][2], acc[mt][nt][3]);
        }
    }
}

// ---------------------------------------------------------------------------
// K4: register transpose. Block = one b, 512 threads = one k each.
// Reads g_sim[i][b][k] (coalesced, MLP 40), writes md[b][k*40+i] as 10x float4
// streaming stores; fused class sums + logits.
// ---------------------------------------------------------------------------
__global__ void __launch_bounds__(512) k_trans(float* __restrict__ md,
                                               float* __restrict__ logits) {
    __shared__ float ws[16];
    __shared__ float totsh;
    const int b = blockIdx.x, t = threadIdx.x;   // t = k

    float v[NI];
    float s = 0.f;
    #pragma unroll
    for (int i = 0; i < NI; i++) {
        v[i] = g_sim[((size_t)i * NB + b) * NK + t];
        s += v[i];
    }

    float4* dst = reinterpret_cast<float4*>(md + (size_t)b * NP + t * NI);
    #pragma unroll
    for (int j = 0; j < 10; j++)
        __stcs(dst + j, make_float4(-v[4 * j], -v[4 * j + 1],
                                    -v[4 * j + 2], -v[4 * j + 3]));

    float w = s;
    #pragma unroll
    for (int off = 16; off > 0; off >>= 1) w += __shfl_xor_sync(0xffffffffu, w, off);
    if ((t & 31) == 0) ws[t >> 5] = w;
    __syncthreads();
    if (t < 32) {
        float u = (t < 16) ? ws[t] : 0.f;
        #pragma unroll
        for (int off = 8; off > 0; off >>= 1) u += __shfl_xor_sync(0xffffffffu, u, off);
        if (t == 0) totsh = u;
    }
    __syncthreads();
    logits[(size_t)b * NK + t] = 1.5f * s - 0.5f * totsh;
}

// ---------------------------------------------------------------------------
extern "C" void kernel_launch(void* const* d_in, const int* in_sizes, int n_in,
                              void* d_out, int out_size) {
    const float* conv  = (const float*)d_in[0];   // (1024, 64, 1, 40)
    const float* proto = (const float*)d_in[1];   // (20480, 64, 1, 1)
    // d_in[2], d_in[3] analytic — unused.

    float* out    = (float*)d_out;
    float* logits = out;                                // (1024, 512)
    float* md     = out + (size_t)NB * NK;              // (1024, 20480)

    cudaFuncSetAttribute(k_gemm_mma, cudaFuncAttributeMaxDynamicSharedMemorySize, GEMM_SMEM);

    k_prep_x<<<NB, 256>>>(conv);
    k_prep_p<<<NP / 4, 256>>>(proto);
    k_gemm_mma<<<dim3(8, 8, NI), 128, GEMM_SMEM>>>();
    k_trans<<<NB, 512>>>(md, logits);
}

// round 6
// speedup vs baseline: 5.5293x; 1.4010x over previous
#include <cuda_runtime.h>
#include <cuda_fp16.h>
#include <cstdint>

#define NB 1024
#define NC 64
#define NI 40
#define NK 512
#define NP 20480   // NK * NI

// ---------------- device scratch (no allocation allowed) ----------------
__device__ __align__(16) __half g_xh[NI * NB * NC];           // [i][b][c]
__device__ __align__(16) __half g_ph[NI * NK * NC];           // [i][k][c]
__device__ __align__(16) float g_scls[NB * NK];               // class sums

// SW128 swizzle on byte offsets (128B rows)
#define SW128(o) ((o) ^ (((o) >> 3) & 0x70))

__device__ __forceinline__ uint32_t smem_u32(const void* p) {
    uint32_t a;
    asm("{ .reg .u64 t; cvta.to.shared.u64 t, %1; cvt.u32.u64 %0, t; }" : "=r"(a) : "l"(p));
    return a;
}
__device__ __forceinline__ void ldsm_x4(uint32_t* r, uint32_t addr) {
    asm volatile("ldmatrix.sync.aligned.m8n8.x4.shared.b16 {%0,%1,%2,%3}, [%4];"
                 : "=r"(r[0]), "=r"(r[1]), "=r"(r[2]), "=r"(r[3]) : "r"(addr));
}
__device__ __forceinline__ void mma16816(float* c, const uint32_t* a, const uint32_t* b) {
    asm volatile(
        "mma.sync.aligned.m16n8k16.row.col.f32.f16.f16.f32 "
        "{%0,%1,%2,%3}, {%4,%5,%6,%7}, {%8,%9}, {%0,%1,%2,%3};"
        : "+f"(c[0]), "+f"(c[1]), "+f"(c[2]), "+f"(c[3])
        : "r"(a[0]), "r"(a[1]), "r"(a[2]), "r"(a[3]), "r"(b[0]), "r"(b[1]));
}
__device__ __forceinline__ void cpa16(uint32_t s, const void* g) {
    asm volatile("{ .reg .u64 gg; cvta.to.global.u64 gg, %1; "
                 "cp.async.cg.shared.global [%0], [gg], 16; }"
                 :: "r"(s), "l"(g) : "memory");
}
#define CP_COMMIT() asm volatile("cp.async.commit_group;" ::: "memory")
#define CP_WAIT1()  asm volatile("cp.async.wait_group 1;" ::: "memory")
#define CP_WAIT0()  asm volatile("cp.async.wait_group 0;" ::: "memory")

// ---------------------------------------------------------------------------
// K1: normalize x over C, convert fp16, write [i=w][b][c]
// ---------------------------------------------------------------------------
__global__ void k_prep_x(const float* __restrict__ conv) {
    __shared__ float sx[NC * NI];
    __shared__ float sinv[NI];
    const int b = blockIdx.x, t = threadIdx.x;
    const float* src = conv + (size_t)b * NC * NI;
    for (int j = t; j < NC * NI; j += 256) sx[j] = src[j];
    __syncthreads();
    if (t < NI) {
        float ss = 0.f;
        #pragma unroll
        for (int c = 0; c < NC; c++) { float v = sx[c * NI + t]; ss += v * v; }
        sinv[t] = 1.f / fmaxf(sqrtf(ss), 1e-12f);
    }
    __syncthreads();
    for (int j = t; j < NI * NC; j += 256) {
        int w = j >> 6, c = j & 63;
        float val = sx[c * NI + w] * sinv[w];
        g_xh[((size_t)w * NB + b) * NC + c] = __float2half_rn(val);
    }
}

// ---------------------------------------------------------------------------
// K2: normalize prototypes over C, convert fp16, write [i][k][c]
// ---------------------------------------------------------------------------
__global__ void k_prep_p(const float* __restrict__ proto) {
    __shared__ float sq[256];
    __shared__ float sinv[4];
    const int t = threadIdx.x;
    const int p = blockIdx.x * 4 + (t >> 6);
    const int c = t & 63;
    float v = proto[(size_t)p * NC + c];
    sq[t] = v * v;
    __syncthreads();
    if ((t & 63) < 32) {
        float w = sq[t] + sq[t + 32];
        #pragma unroll
        for (int off = 16; off > 0; off >>= 1) w += __shfl_xor_sync(0xffffffffu, w, off);
        if ((t & 31) == 0) sinv[t >> 6] = 1.f / fmaxf(sqrtf(w), 1e-12f);
    }
    __syncthreads();
    float val = v * sinv[t >> 6];
    const int k = p / NI, i = p - k * NI;
    g_ph[((size_t)i * NK + k) * NC + c] = __float2half_rn(val);
}

// ---------------------------------------------------------------------------
// K3 (fused): per CTA: 32 b x 32 k x all 40 i.  256 threads, 8 warps
// = 2 i-slots x (2m x 2n), warp tile m16 n16 k64.  Results staged in smem
// [b][k*40+i] then written to md coalesced; class sums in regs -> g_scls.
// ---------------------------------------------------------------------------
#define ST_STRIDE 1284                     // words per staging row (32 rows)
#define OFF_A     (32 * ST_STRIDE * 4)     // 164352
#define OFF_B     (OFF_A + 16384)          // 180736
#define OFF_CLS   (OFF_B + 16384)          // 197120
#define CLS_STRIDE 33
#define FUSED_SMEM (OFF_CLS + 2 * 32 * CLS_STRIDE * 4)   // 205568

__device__ __forceinline__ void issue_loads(uint32_t sb, int it, int stg,
                                            int t, int b0, int k0) {
    const int row = t >> 3, col = t & 7;
    const uint32_t sw = SW128(row * 128 + col * 16);
    #pragma unroll
    for (int q = 0; q < 2; q++) {
        const int i = 2 * it + q;
        cpa16(sb + OFF_A + stg * 8192 + q * 4096 + sw,
              g_xh + ((size_t)i * NB + b0 + row) * NC + col * 8);
        cpa16(sb + OFF_B + stg * 8192 + q * 4096 + sw,
              g_ph + ((size_t)i * NK + k0 + row) * NC + col * 8);
    }
}

__global__ void __launch_bounds__(256, 1) k_fused(float* __restrict__ md) {
    extern __shared__ float smf[];
    const uint32_t sb = smem_u32(smf);
    const int t = threadIdx.x, lane = t & 31, wid = t >> 5;
    const int iw = wid >> 2;                // i slot within pair
    const int wm = (wid >> 1) & 1, wn = wid & 1;
    const int b0 = blockIdx.x * 32;
    const int k0 = blockIdx.y * 32;

    // ldmatrix lane addressing
    const int r8 = lane & 7, g = lane >> 3;
    const uint32_t a_row = (uint32_t)(wm * 16 + (g & 1) * 8 + r8);
    const uint32_t a_kh  = (uint32_t)(g >> 1);
    const uint32_t b_row = (uint32_t)(wn * 16 + (g >> 1) * 8 + r8);
    const uint32_t b_kh  = (uint32_t)(g & 1);

    // output positions
    const int out_r  = wm * 16 + (lane >> 2);
    const int out_k  = wn * 16 + 2 * (lane & 3);

    float cs[8];
    #pragma unroll
    for (int q = 0; q < 8; q++) cs[q] = 0.f;

    issue_loads(sb, 0, 0, t, b0, k0);
    CP_COMMIT();

    for (int it = 0; it < 20; it++) {
        const int stg = it & 1;
        if (it < 19) {
            issue_loads(sb, it + 1, stg ^ 1, t, b0, k0);
            CP_COMMIT();
            CP_WAIT1();
        } else {
            CP_WAIT0();
        }
        __syncthreads();

        const uint32_t Ab = sb + OFF_A + stg * 8192 + iw * 4096;
        const uint32_t Bb = sb + OFF_B + stg * 8192 + iw * 4096;

        uint32_t af[4][4], bf0[4][2], bf1[4][2];
        #pragma unroll
        for (int kc = 0; kc < 4; kc++) {
            ldsm_x4(af[kc], Ab + SW128(a_row * 128 + (kc * 2 + a_kh) * 16));
            uint32_t r[4];
            ldsm_x4(r, Bb + SW128(b_row * 128 + (kc * 2 + b_kh) * 16));
            bf0[kc][0] = r[0]; bf0[kc][1] = r[1];
            bf1[kc][0] = r[2]; bf1[kc][1] = r[3];
        }
        float acc0[4] = {0.f, 0.f, 0.f, 0.f};
        float acc1[4] = {0.f, 0.f, 0.f, 0.f};
        #pragma unroll
        for (int kc = 0; kc < 4; kc++) {
            mma16816(acc0, af[kc], bf0[kc]);
            mma16816(acc1, af[kc], bf1[kc]);
        }

        #pragma unroll
        for (int q = 0; q < 4; q++) { cs[q] += acc0[q]; cs[4 + q] += acc1[q]; }

        // stage into [b][k*40+i]
        const int i = 2 * it + iw;
        smf[out_r * ST_STRIDE + out_k * NI + i]              = acc0[0];
        smf[out_r * ST_STRIDE + (out_k + 1) * NI + i]        = acc0[1];
        smf[(out_r + 8) * ST_STRIDE + out_k * NI + i]        = acc0[2];
        smf[(out_r + 8) * ST_STRIDE + (out_k + 1) * NI + i]  = acc0[3];
        smf[out_r * ST_STRIDE + (out_k + 8) * NI + i]        = acc1[0];
        smf[out_r * ST_STRIDE + (out_k + 9) * NI + i]        = acc1[1];
        smf[(out_r + 8) * ST_STRIDE + (out_k + 8) * NI + i]  = acc1[2];
        smf[(out_r + 8) * ST_STRIDE + (out_k + 9) * NI + i]  = acc1[3];
        __syncthreads();
    }

    // ---- class sums: per-iw partials to smem, combine, store ----
    float* clsb = smf + OFF_CLS / 4;
    clsb[iw * 32 * CLS_STRIDE + out_r * CLS_STRIDE + out_k]           = cs[0];
    clsb[iw * 32 * CLS_STRIDE + out_r * CLS_STRIDE + out_k + 1]       = cs[1];
    clsb[iw * 32 * CLS_STRIDE + (out_r + 8) * CLS_STRIDE + out_k]     = cs[2];
    clsb[iw * 32 * CLS_STRIDE + (out_r + 8) * CLS_STRIDE + out_k + 1] = cs[3];
    clsb[iw * 32 * CLS_STRIDE + out_r * CLS_STRIDE + out_k + 8]       = cs[4];
    clsb[iw * 32 * CLS_STRIDE + out_r * CLS_STRIDE + out_k + 9]       = cs[5];
    clsb[iw * 32 * CLS_STRIDE + (out_r + 8) * CLS_STRIDE + out_k + 8] = cs[6];
    clsb[iw * 32 * CLS_STRIDE + (out_r + 8) * CLS_STRIDE + out_k + 9] = cs[7];
    __syncthreads();

    {
        const int r = t >> 3, kq = (t & 7) * 4;
        float4 v;
        v.x = clsb[r * CLS_STRIDE + kq]     + clsb[32 * CLS_STRIDE + r * CLS_STRIDE + kq];
        v.y = clsb[r * CLS_STRIDE + kq + 1] + clsb[32 * CLS_STRIDE + r * CLS_STRIDE + kq + 1];
        v.z = clsb[r * CLS_STRIDE + kq + 2] + clsb[32 * CLS_STRIDE + r * CLS_STRIDE + kq + 2];
        v.w = clsb[r * CLS_STRIDE + kq + 3] + clsb[32 * CLS_STRIDE + r * CLS_STRIDE + kq + 3];
        *reinterpret_cast<float4*>(&g_scls[(size_t)(b0 + r) * NK + k0 + kq]) = v;
    }

    // ---- md write: coalesced float4 of contiguous 1280-float runs ----
    for (int m = t; m < 32 * 320; m += 256) {
        const int row = m / 320;
        const int off = m - row * 320;
        float4 v = *reinterpret_cast<const float4*>(&smf[row * ST_STRIDE + off * 4]);
        __stcs(reinterpret_cast<float4*>(md + (size_t)(b0 + row) * NP + k0 * NI + off * 4),
               make_float4(-v.x, -v.y, -v.z, -v.w));
    }
}

// ---------------------------------------------------------------------------
// K4: logits[b][cls] = 1.5*S_cls - 0.5*S_total
// ---------------------------------------------------------------------------
__global__ void __launch_bounds__(512) k_logits(float* __restrict__ out) {
    __shared__ float ws[16];
    __shared__ float totsh;
    const int b = blockIdx.x, t = threadIdx.x;
    float s = g_scls[(size_t)b * NK + t];
    float w = s;
    #pragma unroll
    for (int off = 16; off > 0; off >>= 1) w += __shfl_xor_sync(0xffffffffu, w, off);
    if ((t & 31) == 0) ws[t >> 5] = w;
    __syncthreads();
    if (t < 32) {
        float u = (t < 16) ? ws[t] : 0.f;
        #pragma unroll
        for (int off = 8; off > 0; off >>= 1) u += __shfl_xor_sync(0xffffffffu, u, off);
        if (t == 0) totsh = u;
    }
    __syncthreads();
    out[(size_t)b * NK + t] = 1.5f * s - 0.5f * totsh;
}

// ---------------------------------------------------------------------------
extern "C" void kernel_launch(void* const* d_in, const int* in_sizes, int n_in,
                              void* d_out, int out_size) {
    const float* conv  = (const float*)d_in[0];   // (1024, 64, 1, 40)
    const float* proto = (const float*)d_in[1];   // (20480, 64, 1, 1)
    // d_in[2], d_in[3] analytic — unused.

    float* out    = (float*)d_out;
    float* logits = out;                                // (1024, 512)
    float* md     = out + (size_t)NB * NK;              // (1024, 20480)

    cudaFuncSetAttribute(k_fused, cudaFuncAttributeMaxDynamicSharedMemorySize, FUSED_SMEM);

    k_prep_x<<<NB, 256>>>(conv);
    k_prep_p<<<NP / 4, 256>>>(proto);
    k_fused<<<dim3(NB / 32, NK / 32), 256, FUSED_SMEM>>>(md);
    k_logits<<<NB, 512>>>(logits);
}